// round 3
// baseline (speedup 1.0000x reference)
#include <cuda_runtime.h>

// x: [N=256, 3, 3, num=256, F=128] fp32, contiguous.
// out: [N, 3, 3, G=128, F=128] fp32.
// For each group g (num pair 2g, 2g+1): winner = candidate with larger
// rotation angle acos(clip((tr-1)/2,-1,1)); acos decreasing => winner is
// candidate with SMALLER clamp(tr,-1,3); ties -> candidate 0 (argmax first-max).

#define N_    256
#define G_    128
#define F4_   32                      // 128 floats = 32 float4
#define TOT   (N_ * G_ * F4_)         // 1,048,576 threads

// strides in float4 units
#define X_STRIDE_D   8192             // 256*128/4   (per (d1*3+d2) step)
#define X_STRIDE_M   32               // 128/4       (per num step)
#define X_STRIDE_N   73728            // 9*8192
#define O_STRIDE_D   4096             // 128*128/4
#define O_STRIDE_G   32
#define O_STRIDE_N   36864            // 9*4096

__device__ __forceinline__ float clamp_tr(float t) {
    return fminf(fmaxf(t, -1.0f), 3.0f);
}

__global__ __launch_bounds__(256, 4)
void Pooling_5866925326754_kernel(const float4* __restrict__ xv,
                                  float4* __restrict__ ov) {
    int idx = blockIdx.x * blockDim.x + threadIdx.x;
    if (idx >= TOT) return;

    int f4 = idx & (F4_ - 1);
    int g  = (idx >> 5) & (G_ - 1);
    int n  = idx >> 12;

    int ib = n * X_STRIDE_N + (2 * g) * X_STRIDE_M + f4;
    int ob = n * O_STRIDE_N + g * O_STRIDE_G + f4;

    // Front-batch all 18 coalesced 128B loads for max MLP.
    float4 a[9], b[9];
#pragma unroll
    for (int d = 0; d < 9; d++) {
        a[d] = xv[ib + d * X_STRIDE_D];
        b[d] = xv[ib + X_STRIDE_M + d * X_STRIDE_D];
    }

    // traces (diagonal positions 0, 4, 8)
    float t0x = a[0].x + a[4].x + a[8].x;
    float t0y = a[0].y + a[4].y + a[8].y;
    float t0z = a[0].z + a[4].z + a[8].z;
    float t0w = a[0].w + a[4].w + a[8].w;
    float t1x = b[0].x + b[4].x + b[8].x;
    float t1y = b[0].y + b[4].y + b[8].y;
    float t1z = b[0].z + b[4].z + b[8].z;
    float t1w = b[0].w + b[4].w + b[8].w;

    // candidate 1 wins only on strictly larger angle == strictly smaller
    // clamped trace (matches argmax first-max tie rule).
    bool sx = clamp_tr(t1x) < clamp_tr(t0x);
    bool sy = clamp_tr(t1y) < clamp_tr(t0y);
    bool sz = clamp_tr(t1z) < clamp_tr(t0z);
    bool sw = clamp_tr(t1w) < clamp_tr(t0w);

#pragma unroll
    for (int d = 0; d < 9; d++) {
        float4 r;
        r.x = sx ? b[d].x : a[d].x;
        r.y = sy ? b[d].y : a[d].y;
        r.z = sz ? b[d].z : a[d].z;
        r.w = sw ? b[d].w : a[d].w;
        ov[ob + d * O_STRIDE_D] = r;
    }
}

extern "C" void kernel_launch(void* const* d_in, const int* in_sizes, int n_in,
                              void* d_out, int out_size) {
    const float4* x = (const float4*)d_in[0];
    float4* out = (float4*)d_out;
    (void)in_sizes; (void)n_in; (void)out_size;
    Pooling_5866925326754_kernel<<<TOT / 256, 256>>>(x, out);
}

// round 4
// speedup vs baseline: 1.0009x; 1.0009x over previous
#include <cuda_runtime.h>

// x: [N=256, 3, 3, num=256, F=128] fp32, contiguous.
// out: [N, 3, 3, G=128, F=128] fp32.
// For each group g (num pair 2g, 2g+1): winner = candidate with larger
// rotation angle acos(clip((tr-1)/2,-1,1)); acos decreasing => winner is
// candidate with SMALLER clamp(tr,-1,3); ties -> candidate 0 (argmax first-max).

#define N_    256
#define G_    128
#define F4_   32                      // 128 floats = 32 float4
#define TOT   (N_ * G_ * F4_)         // 1,048,576 threads

// strides in float4 units
#define X_STRIDE_D   8192             // 256*128/4   (per (d1*3+d2) step)
#define X_STRIDE_M   32               // 128/4       (per num step)
#define X_STRIDE_N   73728            // 9*8192
#define O_STRIDE_D   4096             // 128*128/4
#define O_STRIDE_G   32
#define O_STRIDE_N   36864            // 9*4096

__device__ __forceinline__ float clamp_tr(float t) {
    return fminf(fmaxf(t, -1.0f), 3.0f);
}

__global__ __launch_bounds__(256, 4)
void Pooling_5866925326754_kernel(const float4* __restrict__ xv,
                                  float4* __restrict__ ov) {
    int idx = blockIdx.x * blockDim.x + threadIdx.x;
    if (idx >= TOT) return;

    int f4 = idx & (F4_ - 1);
    int g  = (idx >> 5) & (G_ - 1);
    int n  = idx >> 12;

    int ib = n * X_STRIDE_N + (2 * g) * X_STRIDE_M + f4;
    int ob = n * O_STRIDE_N + g * O_STRIDE_G + f4;

    // Front-batch all 18 coalesced 128B loads for max MLP.
    float4 a[9], b[9];
#pragma unroll
    for (int d = 0; d < 9; d++) {
        a[d] = xv[ib + d * X_STRIDE_D];
        b[d] = xv[ib + X_STRIDE_M + d * X_STRIDE_D];
    }

    // traces (diagonal positions 0, 4, 8)
    float t0x = a[0].x + a[4].x + a[8].x;
    float t0y = a[0].y + a[4].y + a[8].y;
    float t0z = a[0].z + a[4].z + a[8].z;
    float t0w = a[0].w + a[4].w + a[8].w;
    float t1x = b[0].x + b[4].x + b[8].x;
    float t1y = b[0].y + b[4].y + b[8].y;
    float t1z = b[0].z + b[4].z + b[8].z;
    float t1w = b[0].w + b[4].w + b[8].w;

    // candidate 1 wins only on strictly larger angle == strictly smaller
    // clamped trace (matches argmax first-max tie rule).
    bool sx = clamp_tr(t1x) < clamp_tr(t0x);
    bool sy = clamp_tr(t1y) < clamp_tr(t0y);
    bool sz = clamp_tr(t1z) < clamp_tr(t0z);
    bool sw = clamp_tr(t1w) < clamp_tr(t0w);

#pragma unroll
    for (int d = 0; d < 9; d++) {
        float4 r;
        r.x = sx ? b[d].x : a[d].x;
        r.y = sy ? b[d].y : a[d].y;
        r.z = sz ? b[d].z : a[d].z;
        r.w = sw ? b[d].w : a[d].w;
        ov[ob + d * O_STRIDE_D] = r;
    }
}

extern "C" void kernel_launch(void* const* d_in, const int* in_sizes, int n_in,
                              void* d_out, int out_size) {
    const float4* x = (const float4*)d_in[0];
    float4* out = (float4*)d_out;
    (void)in_sizes; (void)n_in; (void)out_size;
    Pooling_5866925326754_kernel<<<TOT / 256, 256>>>(x, out);
}